// round 1
// baseline (speedup 1.0000x reference)
#include <cuda_runtime.h>
#include <math.h>

// Problem constants (fixed by reference)
#define NN   8192
#define EMB  125
#define POSD 3
#define FIN  128     // EMB + POSD
#define HID  512
#define SLOTS 256    // max neighbors per row (avg ~33, binomial tail makes >128 impossible)

// ---------------- device scratch (no allocation allowed) ----------------
__device__ int   g_col[NN * SLOTS];   // ELL column indices, 8 MB
__device__ int   g_deg[NN];
__device__ float g_norm[NN];          // rsqrt(max(deg,1)); symmetric => in==out
__device__ float g_bufA[NN * HID];    // 16 MB
__device__ float g_bufB[NN * HID];    // 16 MB

// ---------------- 1) build sparse structure + norms ----------------
// One warp per row; ballot-compaction keeps column order (deterministic sums).
__global__ void build_kernel(const float* __restrict__ adj) {
    int warp = threadIdx.x >> 5;
    int lane = threadIdx.x & 31;
    int row  = blockIdx.x * (blockDim.x >> 5) + warp;
    if (row >= NN) return;

    const float* arow = adj + (size_t)row * NN;
    int cnt = 0;
    for (int c0 = 0; c0 < NN; c0 += 32) {
        int c = c0 + lane;
        float v = arow[c];
        bool pred = (v != 0.0f) && (c != row);
        unsigned mask = __ballot_sync(0xFFFFFFFFu, pred);
        int pos = cnt + __popc(mask & ((1u << lane) - 1u));
        if (pred && pos < SLOTS) g_col[row * SLOTS + pos] = c;
        cnt += __popc(mask);
    }
    if (lane == 0) {
        g_deg[row]  = (cnt < SLOTS) ? cnt : SLOTS;
        g_norm[row] = rsqrtf(fmaxf((float)cnt, 1.0f));
    }
}

// ---------------- 2) concat emb||pos -> feat [NN, FIN] ----------------
__global__ void concat_kernel(const float* __restrict__ emb,
                              const float* __restrict__ pos,
                              float* __restrict__ out) {
    int idx = blockIdx.x * blockDim.x + threadIdx.x;
    if (idx >= NN * FIN) return;
    int i = idx / FIN, c = idx % FIN;
    out[idx] = (c < EMB) ? emb[i * EMB + c] : pos[i * POSD + (c - EMB)];
}

// ---------------- 3) SpMM: agg[i,:] = norm[i] * sum_j norm[j]*feat[j,:] ----------------
// One block per dst row; blockDim == feature width C (128 or 512).
__global__ void spmm_kernel(const float* __restrict__ feat,
                            float* __restrict__ agg, int C) {
    int i = blockIdx.x;
    int d = g_deg[i];
    __shared__ int   sc[SLOTS];
    __shared__ float sw[SLOTS];
    for (int k = threadIdx.x; k < d; k += blockDim.x) {
        int j = g_col[i * SLOTS + k];
        sc[k] = j;
        sw[k] = g_norm[j];
    }
    __syncthreads();
    int c = threadIdx.x;
    float acc = 0.0f;
    for (int k = 0; k < d; k++) {
        acc += sw[k] * feat[(size_t)sc[k] * C + c];
    }
    agg[(size_t)i * C + c] = acc * g_norm[i];
}

// ---------------- 4) GEMM + bias + softplus ----------------
// C[M,512] = softplus(A[M,K] @ B[K,512] + bias), M=8192, K in {128,512}.
// BM=128, BN=64, BK=16, 256 threads, 8x4 per-thread microtile.
template <int K>
__global__ void gemm_softplus(const float* __restrict__ A,
                              const float* __restrict__ B,
                              const float* __restrict__ bias,
                              float* __restrict__ Cout) {
    constexpr int BM = 128, BN = 64, BK = 16;
    __shared__ float As[BK][BM];
    __shared__ float Bs[BK][BN];

    int tid = threadIdx.x;          // 0..255
    int tx  = tid & 15;             // N direction (16 * 4 = 64)
    int ty  = tid >> 4;             // M direction (16 * 8 = 128)
    int m0  = blockIdx.y * BM;
    int n0  = blockIdx.x * BN;

    float acc[8][4];
#pragma unroll
    for (int i = 0; i < 8; i++)
#pragma unroll
        for (int j = 0; j < 4; j++) acc[i][j] = 0.0f;

    for (int k0 = 0; k0 < K; k0 += BK) {
        // A tile: 128x16 = 512 float4, 2 per thread, stored transposed
#pragma unroll
        for (int i = 0; i < 2; i++) {
            int f  = tid * 2 + i;           // 0..511
            int r  = f >> 2;                // row in tile (0..127)
            int c4 = (f & 3) * 4;           // col in tile
            float4 v = *(const float4*)&A[(size_t)(m0 + r) * K + k0 + c4];
            As[c4 + 0][r] = v.x;
            As[c4 + 1][r] = v.y;
            As[c4 + 2][r] = v.z;
            As[c4 + 3][r] = v.w;
        }
        // B tile: 16x64 = 256 float4, 1 per thread (B row stride is 512 always)
        {
            int r  = tid >> 4;              // 0..15
            int c4 = (tid & 15) * 4;
            float4 v = *(const float4*)&B[(size_t)(k0 + r) * HID + n0 + c4];
            *(float4*)&Bs[r][c4] = v;
        }
        __syncthreads();

#pragma unroll
        for (int k = 0; k < BK; k++) {
            float4 a0 = *(const float4*)&As[k][ty * 8];
            float4 a1 = *(const float4*)&As[k][ty * 8 + 4];
            float4 b0 = *(const float4*)&Bs[k][tx * 4];
            float a[8] = {a0.x, a0.y, a0.z, a0.w, a1.x, a1.y, a1.z, a1.w};
            float b[4] = {b0.x, b0.y, b0.z, b0.w};
#pragma unroll
            for (int i = 0; i < 8; i++)
#pragma unroll
                for (int j = 0; j < 4; j++) acc[i][j] = fmaf(a[i], b[j], acc[i][j]);
        }
        __syncthreads();
    }

    // epilogue: bias + softplus, stable form matching jax.nn.softplus
#pragma unroll
    for (int i = 0; i < 8; i++) {
        int m = m0 + ty * 8 + i;
#pragma unroll
        for (int j = 0; j < 4; j++) {
            int n = n0 + tx * 4 + j;
            float x = acc[i][j] + bias[n];
            float sp = fmaxf(x, 0.0f) + log1pf(expf(-fabsf(x)));
            Cout[(size_t)m * HID + n] = sp;
        }
    }
}

// ---------------- launch ----------------
extern "C" void kernel_launch(void* const* d_in, const int* in_sizes, int n_in,
                              void* d_out, int out_size) {
    const float* atom_pos = (const float*)d_in[0];
    const float* dist_adj = (const float*)d_in[1];
    const float* atom_emb = (const float*)d_in[2];
    const float* W0 = (const float*)d_in[3];
    const float* b0 = (const float*)d_in[4];
    const float* W1 = (const float*)d_in[5];
    const float* b1 = (const float*)d_in[6];
    const float* W2 = (const float*)d_in[7];
    const float* b2 = (const float*)d_in[8];
    const float* W3 = (const float*)d_in[9];
    const float* b3 = (const float*)d_in[10];
    float* out = (float*)d_out;

    float *bufA, *bufB;
    cudaGetSymbolAddress((void**)&bufA, g_bufA);
    cudaGetSymbolAddress((void**)&bufB, g_bufB);

    // 1) sparse structure + degree norms (8 warps/block -> 8 rows/block)
    build_kernel<<<NN / 8, 256>>>(dist_adj);

    // 2) feat0 = concat(emb, pos) into bufA ([NN, FIN])
    concat_kernel<<<(NN * FIN + 255) / 256, 256>>>(atom_emb, atom_pos, bufA);

    dim3 ggrid(HID / 64, NN / 128);

    // Layer 0: K = FIN = 128
    spmm_kernel<<<NN, FIN>>>(bufA, bufB, FIN);
    gemm_softplus<FIN><<<ggrid, 256>>>(bufB, W0, b0, bufA);

    // Layer 1
    spmm_kernel<<<NN, HID>>>(bufA, bufB, HID);
    gemm_softplus<HID><<<ggrid, 256>>>(bufB, W1, b1, bufA);

    // Layer 2
    spmm_kernel<<<NN, HID>>>(bufA, bufB, HID);
    gemm_softplus<HID><<<ggrid, 256>>>(bufB, W2, b2, bufA);

    // Layer 3 -> write directly to d_out
    spmm_kernel<<<NN, HID>>>(bufA, bufB, HID);
    gemm_softplus<HID><<<ggrid, 256>>>(bufB, W3, b3, out);
}

// round 2
// speedup vs baseline: 1.8656x; 1.8656x over previous
#include <cuda_runtime.h>
#include <math.h>
#include <stdint.h>

// Problem constants (fixed by reference)
#define NN   8192
#define EMB  125
#define POSD 3
#define FIN  128     // EMB + POSD
#define HID  512
#define SLOTS 256

// ---------------- device scratch (no allocation allowed) ----------------
__device__ int   g_col[NN * SLOTS];
__device__ int   g_deg[NN];
__device__ float g_norm[NN];
__device__ float g_bufA[NN * HID];
__device__ float g_bufB[NN * HID];

// ---------------- 1) build sparse structure + norms ----------------
__global__ void build_kernel(const float* __restrict__ adj) {
    int warp = threadIdx.x >> 5;
    int lane = threadIdx.x & 31;
    int row  = blockIdx.x * (blockDim.x >> 5) + warp;
    if (row >= NN) return;

    const float* arow = adj + (size_t)row * NN;
    int cnt = 0;
    for (int c0 = 0; c0 < NN; c0 += 32) {
        int c = c0 + lane;
        float v = arow[c];
        bool pred = (v != 0.0f) && (c != row);
        unsigned mask = __ballot_sync(0xFFFFFFFFu, pred);
        int pos = cnt + __popc(mask & ((1u << lane) - 1u));
        if (pred && pos < SLOTS) g_col[row * SLOTS + pos] = c;
        cnt += __popc(mask);
    }
    if (lane == 0) {
        g_deg[row]  = (cnt < SLOTS) ? cnt : SLOTS;
        g_norm[row] = rsqrtf(fmaxf((float)cnt, 1.0f));
    }
}

// ---------------- 2) concat emb||pos -> feat [NN, FIN] ----------------
__global__ void concat_kernel(const float* __restrict__ emb,
                              const float* __restrict__ pos,
                              float* __restrict__ out) {
    int idx = blockIdx.x * blockDim.x + threadIdx.x;
    if (idx >= NN * FIN) return;
    int i = idx / FIN, c = idx % FIN;
    out[idx] = (c < EMB) ? emb[i * EMB + c] : pos[i * POSD + (c - EMB)];
}

// ---------------- 3) SpMM (float4 per thread, one block per dst row) ----------------
__global__ void spmm_kernel(const float* __restrict__ feat,
                            float* __restrict__ agg, int C) {
    int i = blockIdx.x;
    int d = g_deg[i];
    __shared__ int   sc[SLOTS];
    __shared__ float sw[SLOTS];
    for (int k = threadIdx.x; k < d; k += blockDim.x) {
        int j = g_col[i * SLOTS + k];
        sc[k] = j;
        sw[k] = g_norm[j];
    }
    __syncthreads();
    int c4 = threadIdx.x * 4;
    float4 acc = make_float4(0.f, 0.f, 0.f, 0.f);
    for (int k = 0; k < d; k++) {
        float w = sw[k];
        float4 v = *(const float4*)&feat[(size_t)sc[k] * C + c4];
        acc.x = fmaf(w, v.x, acc.x);
        acc.y = fmaf(w, v.y, acc.y);
        acc.z = fmaf(w, v.z, acc.z);
        acc.w = fmaf(w, v.w, acc.w);
    }
    float ni = g_norm[i];
    acc.x *= ni; acc.y *= ni; acc.z *= ni; acc.w *= ni;
    *(float4*)&agg[(size_t)i * C + c4] = acc;
}

// ---------------- 4) TF32 tensor-core GEMM + bias + softplus ----------------
// C[M,512] = softplus(A[M,K] @ B[K,512] + bias), via mma.sync.m16n8k8.tf32.
// Block tile 128x128, BK=16, 256 threads (8 warps, 2x4), warp tile 64x32.
__device__ __forceinline__ uint32_t f2tf32(float f) {
    uint32_t r;
    asm("cvt.rna.tf32.f32 %0, %1;" : "=r"(r) : "f"(f));
    return r;
}

__device__ __forceinline__ void mma_tf32(float* d, const uint32_t* a, const uint32_t* b) {
    asm volatile(
        "mma.sync.aligned.m16n8k8.row.col.f32.tf32.tf32.f32 "
        "{%0,%1,%2,%3}, {%4,%5,%6,%7}, {%8,%9}, {%0,%1,%2,%3};\n"
        : "+f"(d[0]), "+f"(d[1]), "+f"(d[2]), "+f"(d[3])
        : "r"(a[0]), "r"(a[1]), "r"(a[2]), "r"(a[3]), "r"(b[0]), "r"(b[1]));
}

template <int K>
__global__ __launch_bounds__(256) void gemm_tf32_softplus(
    const float* __restrict__ A,
    const float* __restrict__ Bw,
    const float* __restrict__ bias,
    float* __restrict__ Cout)
{
    constexpr int BM = 128, BN = 128, BK = 16;
    constexpr int LDA = BM + 8;   // 136: stride % 32 == 8 -> conflict-free frag loads
    constexpr int LDB = BN + 8;

    __shared__ uint32_t As[2][BK][LDA];   // A stored transposed: As[k][m]
    __shared__ uint32_t Bs[2][BK][LDB];   // Bs[k][n]

    int tid  = threadIdx.x;
    int lane = tid & 31;
    int warp = tid >> 5;
    int g    = lane >> 2;     // 0..7
    int tg   = lane & 3;      // 0..3
    int wm   = (warp & 1) * 64;
    int wn   = (warp >> 1) * 32;
    int m0   = blockIdx.y * BM;
    int n0   = blockIdx.x * BN;

    float acc[4][4][4];
#pragma unroll
    for (int i = 0; i < 4; i++)
#pragma unroll
        for (int j = 0; j < 4; j++)
#pragma unroll
            for (int r = 0; r < 4; r++) acc[i][j][r] = 0.0f;

    // per-thread global-load coordinates
    // A: 128x16 = 512 float4; 2/thread: f = tid*2+i -> row f>>2, col (f&3)*4
    // B: 16x128 = 512 float4; 2/thread: f = tid*2+i -> row f>>5, col (f&31)*4
    float4 pa[2], pb[2];

    auto loadg = [&](int k0) {
#pragma unroll
        for (int i = 0; i < 2; i++) {
            int f  = tid * 2 + i;
            int ra = f >> 2,  ca = (f & 3) * 4;
            pa[i] = *(const float4*)&A[(size_t)(m0 + ra) * K + k0 + ca];
            int rb = f >> 5,  cb = (f & 31) * 4;
            pb[i] = *(const float4*)&Bw[(size_t)(k0 + rb) * HID + n0 + cb];
        }
    };
    auto stores = [&](int buf) {
#pragma unroll
        for (int i = 0; i < 2; i++) {
            int f  = tid * 2 + i;
            int ra = f >> 2,  ca = (f & 3) * 4;
            As[buf][ca + 0][ra] = f2tf32(pa[i].x);
            As[buf][ca + 1][ra] = f2tf32(pa[i].y);
            As[buf][ca + 2][ra] = f2tf32(pa[i].z);
            As[buf][ca + 3][ra] = f2tf32(pa[i].w);
            int rb = f >> 5,  cb = (f & 31) * 4;
            Bs[buf][rb][cb + 0] = f2tf32(pb[i].x);
            Bs[buf][rb][cb + 1] = f2tf32(pb[i].y);
            Bs[buf][rb][cb + 2] = f2tf32(pb[i].z);
            Bs[buf][rb][cb + 3] = f2tf32(pb[i].w);
        }
    };
    auto compute = [&](int buf) {
#pragma unroll
        for (int kk = 0; kk < BK; kk += 8) {
            uint32_t a[4][4], b[4][2];
#pragma unroll
            for (int i = 0; i < 4; i++) {
                int m = wm + i * 16 + g;
                a[i][0] = As[buf][kk + tg][m];
                a[i][1] = As[buf][kk + tg][m + 8];
                a[i][2] = As[buf][kk + tg + 4][m];
                a[i][3] = As[buf][kk + tg + 4][m + 8];
            }
#pragma unroll
            for (int j = 0; j < 4; j++) {
                int n = wn + j * 8 + g;
                b[j][0] = Bs[buf][kk + tg][n];
                b[j][1] = Bs[buf][kk + tg + 4][n];
            }
#pragma unroll
            for (int i = 0; i < 4; i++)
#pragma unroll
                for (int j = 0; j < 4; j++)
                    mma_tf32(acc[i][j], a[i], b[j]);
        }
    };

    constexpr int NK = K / BK;
    loadg(0);
    stores(0);
    __syncthreads();
#pragma unroll 1
    for (int t = 0; t < NK; t++) {
        if (t + 1 < NK) loadg((t + 1) * BK);
        compute(t & 1);
        if (t + 1 < NK) {
            stores((t + 1) & 1);
            __syncthreads();
        }
    }

    // epilogue: bias + softplus (matches jax.nn.softplus)
#pragma unroll
    for (int i = 0; i < 4; i++) {
        int row = m0 + wm + i * 16 + g;
#pragma unroll
        for (int j = 0; j < 4; j++) {
            int col = n0 + wn + j * 8 + tg * 2;
            float bx = bias[col], by = bias[col + 1];
            float x0 = acc[i][j][0] + bx;
            float x1 = acc[i][j][1] + by;
            float x2 = acc[i][j][2] + bx;
            float x3 = acc[i][j][3] + by;
            float2 o0, o1;
            o0.x = fmaxf(x0, 0.f) + log1pf(expf(-fabsf(x0)));
            o0.y = fmaxf(x1, 0.f) + log1pf(expf(-fabsf(x1)));
            o1.x = fmaxf(x2, 0.f) + log1pf(expf(-fabsf(x2)));
            o1.y = fmaxf(x3, 0.f) + log1pf(expf(-fabsf(x3)));
            *(float2*)&Cout[(size_t)row * HID + col]       = o0;
            *(float2*)&Cout[(size_t)(row + 8) * HID + col] = o1;
        }
    }
}

// ---------------- launch ----------------
extern "C" void kernel_launch(void* const* d_in, const int* in_sizes, int n_in,
                              void* d_out, int out_size) {
    const float* atom_pos = (const float*)d_in[0];
    const float* dist_adj = (const float*)d_in[1];
    const float* atom_emb = (const float*)d_in[2];
    const float* W0 = (const float*)d_in[3];
    const float* b0 = (const float*)d_in[4];
    const float* W1 = (const float*)d_in[5];
    const float* b1 = (const float*)d_in[6];
    const float* W2 = (const float*)d_in[7];
    const float* b2 = (const float*)d_in[8];
    const float* W3 = (const float*)d_in[9];
    const float* b3 = (const float*)d_in[10];
    float* out = (float*)d_out;

    float *bufA, *bufB;
    cudaGetSymbolAddress((void**)&bufA, g_bufA);
    cudaGetSymbolAddress((void**)&bufB, g_bufB);

    build_kernel<<<NN / 8, 256>>>(dist_adj);
    concat_kernel<<<(NN * FIN + 255) / 256, 256>>>(atom_emb, atom_pos, bufA);

    dim3 ggrid(HID / 128, NN / 128);   // (4, 64)

    // Layer 0: K = FIN = 128
    spmm_kernel<<<NN, FIN / 4>>>(bufA, bufB, FIN);
    gemm_tf32_softplus<FIN><<<ggrid, 256>>>(bufB, W0, b0, bufA);

    // Layer 1
    spmm_kernel<<<NN, HID / 4>>>(bufA, bufB, HID);
    gemm_tf32_softplus<HID><<<ggrid, 256>>>(bufB, W1, b1, bufA);

    // Layer 2
    spmm_kernel<<<NN, HID / 4>>>(bufA, bufB, HID);
    gemm_tf32_softplus<HID><<<ggrid, 256>>>(bufB, W2, b2, bufA);

    // Layer 3 -> write directly to d_out
    spmm_kernel<<<NN, HID / 4>>>(bufA, bufB, HID);
    gemm_tf32_softplus<HID><<<ggrid, 256>>>(bufB, W3, b3, out);
}